// round 9
// baseline (speedup 1.0000x reference)
#include <cuda_runtime.h>
#include <cuda_bf16.h>

// Dead-code-eliminated Net2 BSDE recurrence.
// ARITHMETIC IS BIT-FROZEN to the passing trajectory (rel_err 1.627573e-05):
// chaotic near u=50 (mid-branch slope ~3800*dt), so every FP expression below
// is verbatim from a passing round (R1 branch structure, R5 div3 text).
//
// Round-7/8 change (resubmitted unchanged after an infra failure): the serial
// drift uses REAL if/else-if/else (R1's passing structure). The trajectory
// leaves the mid region after ~1-2 steps and stays in the low branch, whose
// dependent chain is ~24 cyc vs ~40 cyc for the branchless select that must
// always wait on the deep mid chain. Branch arms are verbatim -> bits
// identical whether nvcc if-converts or not.

#define D_DIM   100
#define N_STEPS 40
#define NWARPS  32
#define NTHREADS (NWARPS * 32)   // 1024

__device__ __forceinline__ float div3(float x) {
    // Correctly-rounded x/3 (== FDIV bits): Brisebarre-Muller two-FMA scheme.
    const float C_HI = 0.33333334f;       // RN(1/3)
    const float C_LO = -9.9341075e-09f;   // RN(1/3 - C_HI) = -1/(3*2^25)
    return __fmaf_rn(x, C_HI, x * C_LO);
}

__global__ void net2_u_kernel(const float* __restrict__ x0,
                              const float* __restrict__ tlist,
                              const float* __restrict__ noise,   // (N_STEPS, D, 1)
                              const float* __restrict__ u0,
                              const float* __restrict__ gu0,     // (D, 1)
                              float* __restrict__ out) {
    __shared__ float term3[N_STEPS];
    __shared__ float s_dt[N_STEPS];

    const int tid  = threadIdx.x;
    const int warp = tid >> 5;
    const int lane = tid & 31;

    // Issue serial-phase operand loads with the first load batch.
    float u = 0.0f;
    if (tid == 0) u = u0[0];
    if (tid < N_STEPS) s_dt[tid] = tlist[tid];

    // Frozen per-step dot: lane-stride-32 accumulate + 5-level shuffle tree
    // + s * sqrtf(tlist[k]). Warps 0-7 run two steps interleaved; 8-31 one.
    if (warp < 8) {
        const int k0 = warp, k1 = warp + 32;
        float s0 = 0.0f, s1 = 0.0f;
        const float* n0 = noise + k0 * D_DIM;
        const float* n1 = noise + k1 * D_DIM;
        #pragma unroll
        for (int i = lane; i < D_DIM; i += 32) {
            float gu_i = 0.2f * x0[i] * gu0[i];
            s0 += gu_i * n0[i];
            s1 += gu_i * n1[i];
        }
        #pragma unroll
        for (int off = 16; off > 0; off >>= 1) {
            s0 += __shfl_down_sync(0xFFFFFFFFu, s0, off);
            s1 += __shfl_down_sync(0xFFFFFFFFu, s1, off);
        }
        if (lane == 0) {
            term3[k0] = s0 * sqrtf(tlist[k0]);
            term3[k1] = s1 * sqrtf(tlist[k1]);
        }
    } else {
        const int k = warp;
        float s = 0.0f;
        const float* nk = noise + k * D_DIM;
        #pragma unroll
        for (int i = lane; i < D_DIM; i += 32) {
            float gu_i = 0.2f * x0[i] * gu0[i];
            s += gu_i * nk[i];
        }
        #pragma unroll
        for (int off = 16; off > 0; off >>= 1)
            s += __shfl_down_sync(0xFFFFFFFFu, s, off);
        if (lane == 0)
            term3[k] = s * sqrtf(tlist[k]);
    }

    __syncthreads();

    if (tid == 0) {
        #pragma unroll
        for (int k = 0; k < N_STEPS; k++) {
            float dt = s_dt[k];
            // R1's passing branch structure; R5's passing expressions.
            float f;
            if (u < 50.0f) {
                f = div3(-0.02f * u) - 0.02f * u;
            } else if (u >= 70.0f) {
                f = div3(-0.002f * u) - 0.02f * u;
            } else {
                f = div3(-(70.0f - 50.0f) / (0.02f - 0.2f) * (u - 50.0f)) * u
                    - (0.2f / 3.0f) * u - 0.02f * u;
            }
            u = u - f * dt + term3[k];   // frozen update shape
        }
        out[0] = u;
    }
}

extern "C" void kernel_launch(void* const* d_in, const int* in_sizes, int n_in,
                              void* d_out, int out_size) {
    const float* x0    = (const float*)d_in[0];
    const float* tlist = (const float*)d_in[1];
    const float* noise = (const float*)d_in[2];
    const float* u0    = (const float*)d_in[3];
    const float* gu0   = (const float*)d_in[4];
    float* out = (float*)d_out;

    net2_u_kernel<<<1, NTHREADS>>>(x0, tlist, noise, u0, gu0, out);
}

// round 10
// speedup vs baseline: 1.0885x; 1.0885x over previous
#include <cuda_runtime.h>
#include <cuda_bf16.h>

// Dead-code-eliminated Net2 BSDE recurrence.
// ARITHMETIC IS BIT-FROZEN to the passing trajectory (rel_err 1.627573e-05).
// All FP expressions verbatim from the passing Round-5 kernel (8.19us champ):
// branchless nested-ternary drift + bit-exact two-FMA div3.
//
// Round-9 lesson: real branches in the unrolled serial loop cost BSSY/BSYNC
// and REGRESSED; reverted to R5's branchless loop.
//
// Round-10 change: SPECULATION WITH VERIFIED FALLBACK. u0=50 starts in the
// mid branch; the steep mid drift ejects u deep into u<50 within ~2 steps and
// the stable linear low branch keeps it there. So: k<8 full frozen general
// steps; k>=8 low-branch-only steps (~28 cyc chain vs ~42) with an off-chain
// violation flag (u >= 50). If the flag fires, recompute all 40 steps with
// the general loop -> correct for any input; bit-identical to R5 when the
// speculation holds (it does for this input).

#define D_DIM    100
#define N_STEPS  40
#define N_GEN    8
#define NWARPS   32
#define NTHREADS (NWARPS * 32)   // 1024

__device__ __forceinline__ float div3(float x) {
    // Correctly-rounded x/3 (== FDIV bits): Brisebarre-Muller two-FMA scheme.
    const float C_HI = 0.33333334f;       // RN(1/3)
    const float C_LO = -9.9341075e-09f;   // RN(1/3 - C_HI) = -1/(3*2^25)
    return __fmaf_rn(x, C_HI, x * C_LO);
}

// Frozen R5 general step (branchless nested ternaries).
__device__ __forceinline__ float step_general(float u, float dt, float t3) {
    float low  = div3(-0.02f * u) - 0.02f * u;
    float high = div3(-0.002f * u) - 0.02f * u;
    float mid  = div3(-(70.0f - 50.0f) / (0.02f - 0.2f) * (u - 50.0f)) * u
                 - (0.2f / 3.0f) * u - 0.02f * u;
    float f = (u < 50.0f) ? low : ((u >= 70.0f) ? high : mid);
    return u - f * dt + t3;
}

__global__ void net2_u_kernel(const float* __restrict__ x0,
                              const float* __restrict__ tlist,
                              const float* __restrict__ noise,   // (N_STEPS, D, 1)
                              const float* __restrict__ u0,
                              const float* __restrict__ gu0,     // (D, 1)
                              float* __restrict__ out) {
    __shared__ float term3[N_STEPS];
    __shared__ float s_dt[N_STEPS];

    const int tid  = threadIdx.x;
    const int warp = tid >> 5;
    const int lane = tid & 31;

    // Issue serial-phase operand loads with the first load batch.
    float ustart = 0.0f;
    if (tid == 0) ustart = u0[0];
    if (tid < N_STEPS) s_dt[tid] = tlist[tid];

    // Frozen per-step dot: lane-stride-32 accumulate + 5-level shuffle tree
    // + s * sqrtf(tlist[k]). Warps 0-7 run two steps interleaved; 8-31 one.
    if (warp < 8) {
        const int k0 = warp, k1 = warp + 32;
        float s0 = 0.0f, s1 = 0.0f;
        const float* n0 = noise + k0 * D_DIM;
        const float* n1 = noise + k1 * D_DIM;
        #pragma unroll
        for (int i = lane; i < D_DIM; i += 32) {
            float gu_i = 0.2f * x0[i] * gu0[i];
            s0 += gu_i * n0[i];
            s1 += gu_i * n1[i];
        }
        #pragma unroll
        for (int off = 16; off > 0; off >>= 1) {
            s0 += __shfl_down_sync(0xFFFFFFFFu, s0, off);
            s1 += __shfl_down_sync(0xFFFFFFFFu, s1, off);
        }
        if (lane == 0) {
            term3[k0] = s0 * sqrtf(tlist[k0]);
            term3[k1] = s1 * sqrtf(tlist[k1]);
        }
    } else {
        const int k = warp;
        float s = 0.0f;
        const float* nk = noise + k * D_DIM;
        #pragma unroll
        for (int i = lane; i < D_DIM; i += 32) {
            float gu_i = 0.2f * x0[i] * gu0[i];
            s += gu_i * nk[i];
        }
        #pragma unroll
        for (int off = 16; off > 0; off >>= 1)
            s += __shfl_down_sync(0xFFFFFFFFu, s, off);
        if (lane == 0)
            term3[k] = s * sqrtf(tlist[k]);
    }

    __syncthreads();

    if (tid == 0) {
        float u = ustart;

        // Transient: full frozen general steps.
        #pragma unroll
        for (int k = 0; k < N_GEN; k++)
            u = step_general(u, s_dt[k], term3[k]);

        // Speculative tail: low-branch-only (verbatim low expression),
        // violation flag accumulated OFF the dependency chain.
        bool violated = false;
        #pragma unroll
        for (int k = N_GEN; k < N_STEPS; k++) {
            violated = violated || (u >= 50.0f);
            float f = div3(-0.02f * u) - 0.02f * u;
            u = u - f * s_dt[k] + term3[k];
        }

        if (violated) {
            // Cold fallback: frozen general loop for all 40 steps.
            u = ustart;
            for (int k = 0; k < N_STEPS; k++)
                u = step_general(u, s_dt[k], term3[k]);
        }

        out[0] = u;
    }
}

extern "C" void kernel_launch(void* const* d_in, const int* in_sizes, int n_in,
                              void* d_out, int out_size) {
    const float* x0    = (const float*)d_in[0];
    const float* tlist = (const float*)d_in[1];
    const float* noise = (const float*)d_in[2];
    const float* u0    = (const float*)d_in[3];
    const float* gu0   = (const float*)d_in[4];
    float* out = (float*)d_out;

    net2_u_kernel<<<1, NTHREADS>>>(x0, tlist, noise, u0, gu0, out);
}

// round 11
// speedup vs baseline: 1.0969x; 1.0078x over previous
#include <cuda_runtime.h>
#include <cuda_bf16.h>

// Dead-code-eliminated Net2 BSDE recurrence.
// ARITHMETIC IS BIT-FROZEN to the passing trajectory (rel_err 1.627573e-05).
// All FP expressions verbatim from the passing Round-5 kernel (best: 6.94us
// ncu): branchless drift + bit-exact two-FMA div3.
//
// R9 lesson: real branches in the unrolled loop -> BSSY/BSYNC, regressed.
// R10 lesson: "u<50 forever" speculation is WRONG -- the low-branch drift
// pushes u UP toward 50, so the trajectory hovers at the boundary and
// re-enters the mid region; the fallback executed and we paid for both loops.
//
// R11 (correct speculation): u >= 70 is unreachable from u0=50 (low branch
// caps the climb, mid branch pushes down). Drop only the HIGH arm from the
// select: f = (u<50) ? low : mid  -- removes one FSEL from the 40-iteration
// chain. Guard: umax accumulated OFF-CHAIN via fmaxf (FMNMX, no short-circuit
// branches); single cold check at the end falls back to the full frozen
// general loop -> correct for any input, bit-identical to R5 when u < 70
// throughout (it is).

#define D_DIM    100
#define N_STEPS  40
#define NWARPS   32
#define NTHREADS (NWARPS * 32)   // 1024

__device__ __forceinline__ float div3(float x) {
    // Correctly-rounded x/3 (== FDIV bits): Brisebarre-Muller two-FMA scheme.
    const float C_HI = 0.33333334f;       // RN(1/3)
    const float C_LO = -9.9341075e-09f;   // RN(1/3 - C_HI) = -1/(3*2^25)
    return __fmaf_rn(x, C_HI, x * C_LO);
}

// Frozen R5 general step (all three arms) -- cold fallback only.
__device__ float step_general(float u, float dt, float t3) {
    float low  = div3(-0.02f * u) - 0.02f * u;
    float high = div3(-0.002f * u) - 0.02f * u;
    float mid  = div3(-(70.0f - 50.0f) / (0.02f - 0.2f) * (u - 50.0f)) * u
                 - (0.2f / 3.0f) * u - 0.02f * u;
    float f = (u < 50.0f) ? low : ((u >= 70.0f) ? high : mid);
    return u - f * dt + t3;
}

__global__ void net2_u_kernel(const float* __restrict__ x0,
                              const float* __restrict__ tlist,
                              const float* __restrict__ noise,   // (N_STEPS, D, 1)
                              const float* __restrict__ u0,
                              const float* __restrict__ gu0,     // (D, 1)
                              float* __restrict__ out) {
    __shared__ float term3[N_STEPS];
    __shared__ float s_dt[N_STEPS];

    const int tid  = threadIdx.x;
    const int warp = tid >> 5;
    const int lane = tid & 31;

    // Issue serial-phase operand loads with the first load batch.
    float ustart = 0.0f;
    if (tid == 0) ustart = u0[0];
    if (tid < N_STEPS) s_dt[tid] = tlist[tid];

    // Frozen per-step dot: lane-stride-32 accumulate + 5-level shuffle tree
    // + s * sqrtf(tlist[k]). Warps 0-7 run two steps interleaved; 8-31 one.
    if (warp < 8) {
        const int k0 = warp, k1 = warp + 32;
        float s0 = 0.0f, s1 = 0.0f;
        const float* n0 = noise + k0 * D_DIM;
        const float* n1 = noise + k1 * D_DIM;
        #pragma unroll
        for (int i = lane; i < D_DIM; i += 32) {
            float gu_i = 0.2f * x0[i] * gu0[i];
            s0 += gu_i * n0[i];
            s1 += gu_i * n1[i];
        }
        #pragma unroll
        for (int off = 16; off > 0; off >>= 1) {
            s0 += __shfl_down_sync(0xFFFFFFFFu, s0, off);
            s1 += __shfl_down_sync(0xFFFFFFFFu, s1, off);
        }
        if (lane == 0) {
            term3[k0] = s0 * sqrtf(tlist[k0]);
            term3[k1] = s1 * sqrtf(tlist[k1]);
        }
    } else {
        const int k = warp;
        float s = 0.0f;
        const float* nk = noise + k * D_DIM;
        #pragma unroll
        for (int i = lane; i < D_DIM; i += 32) {
            float gu_i = 0.2f * x0[i] * gu0[i];
            s += gu_i * nk[i];
        }
        #pragma unroll
        for (int off = 16; off > 0; off >>= 1)
            s += __shfl_down_sync(0xFFFFFFFFu, s, off);
        if (lane == 0)
            term3[k] = s * sqrtf(tlist[k]);
    }

    __syncthreads();

    if (tid == 0) {
        float u = ustart;
        float umax = -3.0e38f;

        #pragma unroll
        for (int k = 0; k < N_STEPS; k++) {
            float dt = s_dt[k];
            // Verbatim frozen low/mid expressions; high arm dropped (valid
            // iff u < 70 throughout -- guarded below).
            float low = div3(-0.02f * u) - 0.02f * u;
            float mid = div3(-(70.0f - 50.0f) / (0.02f - 0.2f) * (u - 50.0f)) * u
                        - (0.2f / 3.0f) * u - 0.02f * u;
            float f = (u < 50.0f) ? low : mid;
            umax = fmaxf(umax, u);          // off-chain guard (FMNMX)
            u = u - f * dt + term3[k];      // frozen update shape
        }

        if (umax >= 70.0f) {
            // Cold fallback: full frozen general loop (rolled).
            u = ustart;
            for (int k = 0; k < N_STEPS; k++)
                u = step_general(u, s_dt[k], term3[k]);
        }

        out[0] = u;
    }
}

extern "C" void kernel_launch(void* const* d_in, const int* in_sizes, int n_in,
                              void* d_out, int out_size) {
    const float* x0    = (const float*)d_in[0];
    const float* tlist = (const float*)d_in[1];
    const float* noise = (const float*)d_in[2];
    const float* u0    = (const float*)d_in[3];
    const float* gu0   = (const float*)d_in[4];
    float* out = (float*)d_out;

    net2_u_kernel<<<1, NTHREADS>>>(x0, tlist, noise, u0, gu0, out);
}

// round 12
// speedup vs baseline: 1.3738x; 1.2524x over previous
#include <cuda_runtime.h>
#include <cuda_bf16.h>

// Dead-code-eliminated Net2 BSDE recurrence.
// ARITHMETIC IS BIT-FROZEN to the passing trajectory (rel_err 1.627573e-05).
// Serial loop is verbatim the Round-5 champion (branchless 3-arm select +
// bit-exact two-FMA div3) -- it sits at its frozen-rounding chain floor
// (~44 cyc/iter); R6/R9/R10/R11 all confirmed no serial-side gains.
//
// Round-12 change attacks PHASE 1, which is LSU-ISSUE bound: previously all
// 32 warps redundantly loaded x0/gu0 (~416 warp-LDGs x 1.82cyc ~ 760 cyc of
// SM LSU issue). Now gu_i = 0.2*x0[i]*gu0[i] is computed ONCE into shared by
// threads 0-99 (bit-identical value, consumed via LDS), noise is preloaded
// into registers before the gu barrier (latency hidden), and sqrtf reads
// s_dt instead of re-loading tlist. LDG count ~416 -> ~170.
// Frozen per-lane element assignment (i = lane, +32, +64, +96) and per-
// accumulator add order preserved exactly.

#define D_DIM    100
#define N_STEPS  40
#define NWARPS   32
#define NTHREADS (NWARPS * 32)   // 1024

__device__ __forceinline__ float div3(float x) {
    // Correctly-rounded x/3 (== FDIV bits): Brisebarre-Muller two-FMA scheme.
    const float C_HI = 0.33333334f;       // RN(1/3)
    const float C_LO = -9.9341075e-09f;   // RN(1/3 - C_HI) = -1/(3*2^25)
    return __fmaf_rn(x, C_HI, x * C_LO);
}

__global__ void net2_u_kernel(const float* __restrict__ x0,
                              const float* __restrict__ tlist,
                              const float* __restrict__ noise,   // (N_STEPS, D, 1)
                              const float* __restrict__ u0,
                              const float* __restrict__ gu0,     // (D, 1)
                              float* __restrict__ out) {
    __shared__ float term3[N_STEPS];
    __shared__ float s_dt[N_STEPS];
    __shared__ float gu_s[D_DIM];

    const int tid  = threadIdx.x;
    const int warp = tid >> 5;
    const int lane = tid & 31;

    // ---- Issue all global loads up front ----
    float ustart = 0.0f;
    if (tid == 0) ustart = u0[0];
    if (tid < N_STEPS) s_dt[tid] = tlist[tid];

    // Preload this warp's noise elements (frozen lane mapping: lane, +32,
    // +64, +96; element lane+96 exists only for lane < 4).
    const bool tail = (lane < (D_DIM - 96));   // lane < 4
    float a0, a1, a2, a3 = 0.0f;
    float b0 = 0.0f, b1 = 0.0f, b2 = 0.0f, b3 = 0.0f;
    int k0, k1 = -1;
    if (warp < 8) { k0 = warp; k1 = warp + 32; } else { k0 = warp; }
    {
        const float* n0 = noise + k0 * D_DIM;
        a0 = n0[lane]; a1 = n0[lane + 32]; a2 = n0[lane + 64];
        if (tail) a3 = n0[lane + 96];
        if (k1 >= 0) {
            const float* n1 = noise + k1 * D_DIM;
            b0 = n1[lane]; b1 = n1[lane + 32]; b2 = n1[lane + 64];
            if (tail) b3 = n1[lane + 96];
        }
    }

    // gu computed once (bit-identical expression), consumed by everyone.
    if (tid < D_DIM) gu_s[tid] = 0.2f * x0[tid] * gu0[tid];

    __syncthreads();

    // ---- Frozen dot products from smem gu + register noise ----
    {
        float g0 = gu_s[lane], g1 = gu_s[lane + 32], g2 = gu_s[lane + 64];
        float g3 = tail ? gu_s[lane + 96] : 0.0f;

        if (k1 >= 0) {
            float s0 = 0.0f, s1 = 0.0f;
            s0 += g0 * a0;  s1 += g0 * b0;
            s0 += g1 * a1;  s1 += g1 * b1;
            s0 += g2 * a2;  s1 += g2 * b2;
            if (tail) { s0 += g3 * a3; s1 += g3 * b3; }
            #pragma unroll
            for (int off = 16; off > 0; off >>= 1) {
                s0 += __shfl_down_sync(0xFFFFFFFFu, s0, off);
                s1 += __shfl_down_sync(0xFFFFFFFFu, s1, off);
            }
            if (lane == 0) {
                term3[k0] = s0 * sqrtf(s_dt[k0]);
                term3[k1] = s1 * sqrtf(s_dt[k1]);
            }
        } else {
            float s = 0.0f;
            s += g0 * a0;
            s += g1 * a1;
            s += g2 * a2;
            if (tail) s += g3 * a3;
            #pragma unroll
            for (int off = 16; off > 0; off >>= 1)
                s += __shfl_down_sync(0xFFFFFFFFu, s, off);
            if (lane == 0)
                term3[k0] = s * sqrtf(s_dt[k0]);
        }
    }

    __syncthreads();

    // ---- Verbatim Round-5 serial loop (frozen) ----
    if (tid == 0) {
        float u = ustart;
        #pragma unroll
        for (int k = 0; k < N_STEPS; k++) {
            float dt = s_dt[k];
            float low  = div3(-0.02f * u) - 0.02f * u;
            float high = div3(-0.002f * u) - 0.02f * u;
            float mid  = div3(-(70.0f - 50.0f) / (0.02f - 0.2f) * (u - 50.0f)) * u
                         - (0.2f / 3.0f) * u - 0.02f * u;
            float f = (u < 50.0f) ? low : ((u >= 70.0f) ? high : mid);
            u = u - f * dt + term3[k];
        }
        out[0] = u;
    }
}

extern "C" void kernel_launch(void* const* d_in, const int* in_sizes, int n_in,
                              void* d_out, int out_size) {
    const float* x0    = (const float*)d_in[0];
    const float* tlist = (const float*)d_in[1];
    const float* noise = (const float*)d_in[2];
    const float* u0    = (const float*)d_in[3];
    const float* gu0   = (const float*)d_in[4];
    float* out = (float*)d_out;

    net2_u_kernel<<<1, NTHREADS>>>(x0, tlist, noise, u0, gu0, out);
}